// round 10
// baseline (speedup 1.0000x reference)
#include <cuda_runtime.h>
#include <cuda_bf16.h>
#include <stdint.h>
#include <math.h>

#define NROW 8192
#define THREADS 512
#define NTILES 2080              // 64*65/2 upper-triangle 128x128 tiles
#define GRID 148
#define STRIDE_Q 144u            // bytes per smem tile row (128B data + 16B pad)
#define TILEQ (128u * STRIDE_Q)  // 18432
#define BUFOFF(b) ((uint32_t)(b) * 2u * TILEQ)   // A at +0, B at +TILEQ
#define YOFF   (4u * TILEQ)                       // 73728: 2 bufs x 1024B
#define IP_OFF (YOFF + 2048u)                     // 75776: 3 x 10240B (128 rows x 20 words)
#define JP_OFF (IP_OFF + 30720u)                  // 106496: 3 x 18432B (128 cols x 36 words)
#define SMEM_TOTAL (JP_OFF + 55296u)              // 161792 <= 232448

#define PLANE 524288             // 64*64*128 floats per stat plane
#define INVQ  (1.0f / 16129.0f)  // 1/(127*127)

__device__ uint32_t g_xq[NROW * 32];   // int8-quantized normalized x (4 per u32)
// P[s][a][b][r]: s=0 denom, 1 S, 2 m. Every slot written exactly once per launch.
__device__ float g_P[3 * PLANE];
__device__ float g_part[64];
__device__ int   g_ctr;          // zero-init; self-resets each launch

// ---------------- PTX helpers ----------------
__device__ __forceinline__ uint32_t smem_u32(const void* p) {
    uint32_t a;
    asm("{ .reg .u64 t; cvta.to.shared.u64 t, %1; cvt.u32.u64 %0, t; }" : "=r"(a) : "l"(p));
    return a;
}
#define LDSM4(r, a) \
    asm volatile("ldmatrix.sync.aligned.m8n8.x4.shared.b16 {%0,%1,%2,%3}, [%4];" \
        : "=r"((r)[0]), "=r"((r)[1]), "=r"((r)[2]), "=r"((r)[3]) : "r"(a))
#define IMMA16832(c, a, b0v, b1v) \
    asm volatile("mma.sync.aligned.m16n8k32.row.col.s32.s8.s8.s32 " \
        "{%0,%1,%2,%3}, {%4,%5,%6,%7}, {%8,%9}, {%0,%1,%2,%3};" \
        : "+r"((c)[0]), "+r"((c)[1]), "+r"((c)[2]), "+r"((c)[3]) \
        : "r"((a)[0]), "r"((a)[1]), "r"((a)[2]), "r"((a)[3]), "r"(b0v), "r"(b1v))
#define CP_ASYNC16(dst, src) \
    asm volatile("cp.async.cg.shared.global [%0], [%1], 16;" :: "r"(dst), "l"(src))
#define CP_ASYNC4(dst, src) \
    asm volatile("cp.async.ca.shared.global [%0], [%1], 4;" :: "r"(dst), "l"(src))
#define CP_COMMIT() asm volatile("cp.async.commit_group;" ::: "memory")
#define CP_WAIT1()  asm volatile("cp.async.wait_group 1;" ::: "memory")
#define CP_WAIT0()  asm volatile("cp.async.wait_group 0;" ::: "memory")

// ---------------- Kernel 1: normalize + int8 quantize (2 rows/warp) ----------------
__global__ void __launch_bounds__(256) norm_kernel(const float* __restrict__ x) {
    int warp = threadIdx.x >> 5, lane = threadIdx.x & 31;
    int row0 = (blockIdx.x * 8 + warp) * 2;
    float4 v0 = reinterpret_cast<const float4*>(x)[row0 * 32 + lane];
    float4 v1 = reinterpret_cast<const float4*>(x)[(row0 + 1) * 32 + lane];
    float s0 = v0.x * v0.x + v0.y * v0.y + v0.z * v0.z + v0.w * v0.w;
    float s1 = v1.x * v1.x + v1.y * v1.y + v1.z * v1.z + v1.w * v1.w;
#pragma unroll
    for (int o = 16; o; o >>= 1) {
        s0 += __shfl_xor_sync(0xffffffffu, s0, o);
        s1 += __shfl_xor_sync(0xffffffffu, s1, o);
    }
    float i0 = 127.0f / fmaxf(sqrtf(s0), 1e-12f);
    float i1 = 127.0f / fmaxf(sqrtf(s1), 1e-12f);
    int ax = __float2int_rn(v0.x * i0), ay = __float2int_rn(v0.y * i0);
    int az = __float2int_rn(v0.z * i0), aw = __float2int_rn(v0.w * i0);
    int bx = __float2int_rn(v1.x * i1), by = __float2int_rn(v1.y * i1);
    int bz = __float2int_rn(v1.z * i1), bw = __float2int_rn(v1.w * i1);
    uint32_t q0 = (uint32_t)(ax & 255) | ((uint32_t)(ay & 255) << 8)
                | ((uint32_t)(az & 255) << 16) | ((uint32_t)(aw & 255) << 24);
    uint32_t q1 = (uint32_t)(bx & 255) | ((uint32_t)(by & 255) << 8)
                | ((uint32_t)(bz & 255) << 16) | ((uint32_t)(bw & 255) << 24);
    g_xq[row0 * 32 + lane] = q0;
    g_xq[(row0 + 1) * 32 + lane] = q1;
}

// ---------------- tile id -> (bi, bj), bi <= bj ----------------
__device__ __forceinline__ void tile2bibj(int t, int& bi, int& bj) {
    int rem = (NTILES - 1) - t;
    int k = (int)((__fsqrt_rn(8.0f * (float)rem + 1.0f) - 1.0f) * 0.5f);
    while ((k + 1) * (k + 2) / 2 <= rem) ++k;
    while (k * (k + 1) / 2 > rem) --k;
    int off = rem - k * (k + 1) / 2;
    bi = 63 - k;
    bj = 63 - off;
}

__device__ __forceinline__ void prefetch_tile(uint32_t sbase, int buf,
                                              int bi, int bj, const uint4* xq,
                                              const int* y, int tid) {
    uint32_t dst = sbase + BUFOFF(buf);
    const int arow = bi * 128, brow = bj * 128;
#pragma unroll
    for (int q = 0; q < 2; ++q) {
        int idx = tid + q * THREADS;
        int row = idx >> 3, c16 = idx & 7;
        CP_ASYNC16(dst + row * STRIDE_Q + c16 * 16, (const void*)(xq + (arow + row) * 8 + c16));
    }
#pragma unroll
    for (int q = 0; q < 2; ++q) {
        int idx = tid + q * THREADS;
        int row = idx >> 3, c16 = idx & 7;
        CP_ASYNC16(dst + TILEQ + row * STRIDE_Q + c16 * 16, (const void*)(xq + (brow + row) * 8 + c16));
    }
    if (tid < 128)
        CP_ASYNC4(sbase + YOFF + (uint32_t)buf * 1024u + tid * 4, (const void*)(y + arow + tid));
    else if (tid < 256)
        CP_ASYNC4(sbase + YOFF + (uint32_t)buf * 1024u + 512u + (tid - 128) * 4,
                  (const void*)(y + brow + (tid - 128)));
    CP_COMMIT();
}

// ---------------- Kernel 2: symmetric int8 Gram + dual-orientation stats ----------------
__global__ void __launch_bounds__(THREADS, 1) scl_mma_kernel(const int* __restrict__ y) {
    extern __shared__ char smem[];
    const uint32_t sbase = smem_u32(smem);
    const int tid = threadIdx.x, wid = tid >> 5, lane = tid & 31;
    const int wi = wid & 3, wj = wid >> 2;
    const int grp = lane >> 2;

    const uint4* xq = reinterpret_cast<const uint4*>(g_xq);
    float* ipE = reinterpret_cast<float*>(smem + IP_OFF);          // 128 x 20 words
    float* ipS = ipE + 2560; float* ipM = ipE + 5120;
    float* jpE = reinterpret_cast<float*>(smem + JP_OFF);          // 128 x 36 words
    float* jpS = jpE + 4608; float* jpM = jpE + 9216;

    // relative ldmatrix offsets (byte-identical mapping to bf16 k16: 32 k-bytes/step)
    uint32_t aRel[2], bRel[2];
#pragma unroll
    for (int mi = 0; mi < 2; ++mi)
        aRel[mi] = (uint32_t)((wi * 32 + mi * 16 + (lane & 15)) * STRIDE_Q + (lane >> 4) * 16);
#pragma unroll
    for (int nb = 0; nb < 2; ++nb)
        bRel[nb] = (uint32_t)((wj * 32 + nb * 16 + (lane & 7) + (lane >> 4) * 8) * STRIDE_Q
                   + ((lane >> 3) & 1) * 16);

    int t = blockIdx.x;
    {
        int bi, bj; tile2bibj(t, bi, bj);
        prefetch_tile(sbase, 0, bi, bj, xq, y, tid);
    }

    int it = 0;
    for (; t < NTILES; t += GRID, ++it) {
        int bi, bj; tile2bibj(t, bi, bj);
        const int nt = t + GRID;
        if (nt < NTILES) {
            int nbi, nbj; tile2bibj(nt, nbi, nbj);
            prefetch_tile(sbase, (it + 1) & 1, nbi, nbj, xq, y, tid);
            CP_WAIT1();
        } else {
            CP_WAIT0();
        }
        __syncthreads();

        const uint32_t abase = sbase + BUFOFF(it & 1);
        const uint32_t bbase = abase + TILEQ;
        const int* yI = reinterpret_cast<const int*>(smem + YOFF + (it & 1) * 1024);
        const int* yJ = yI + 128;
        const bool isDiag = (bi == bj);

        int acc[2][4][4];
#pragma unroll
        for (int mi = 0; mi < 2; ++mi)
#pragma unroll
            for (int p = 0; p < 4; ++p)
#pragma unroll
                for (int c = 0; c < 4; ++c) acc[mi][p][c] = 0;

#pragma unroll
        for (int kk = 0; kk < 4; ++kk) {
            uint32_t a0[4], a1[4], b0[4], b1[4];
            LDSM4(a0, abase + aRel[0] + kk * 32);
            LDSM4(a1, abase + aRel[1] + kk * 32);
            LDSM4(b0, bbase + bRel[0] + kk * 32);
            LDSM4(b1, bbase + bRel[1] + kk * 32);
            IMMA16832(acc[0][0], a0, b0[0], b0[1]);
            IMMA16832(acc[0][1], a0, b0[2], b0[3]);
            IMMA16832(acc[0][2], a0, b1[0], b1[1]);
            IMMA16832(acc[0][3], a0, b1[2], b1[3]);
            IMMA16832(acc[1][0], a1, b0[0], b0[1]);
            IMMA16832(acc[1][1], a1, b0[2], b0[3]);
            IMMA16832(acc[1][2], a1, b1[0], b1[1]);
            IMMA16832(acc[1][3], a1, b1[2], b1[3]);
        }

        int yiv[2][2];
#pragma unroll
        for (int mi = 0; mi < 2; ++mi)
#pragma unroll
            for (int rh = 0; rh < 2; ++rh)
                yiv[mi][rh] = yI[wi * 32 + mi * 16 + rh * 8 + grp];

        float dnm[2][2] = {{0.f,0.f},{0.f,0.f}};
        float Ss [2][2] = {{0.f,0.f},{0.f,0.f}};
        float mm [2][2] = {{0.f,0.f},{0.f,0.f}};

        if (!isDiag) {
#pragma unroll
            for (int p = 0; p < 4; ++p) {
                const int jl = wj * 32 + p * 8 + 2 * (lane & 3);
                const int yj0 = yJ[jl], yj1 = yJ[jl + 1];
                float cE0=0.f,cE1=0.f,cS0=0.f,cS1=0.f,cM0=0.f,cM1=0.f;
#pragma unroll
                for (int mi = 0; mi < 2; ++mi)
#pragma unroll
                    for (int rh = 0; rh < 2; ++rh) {
                        const float d0 = (float)acc[mi][p][rh * 2 + 0] * INVQ;
                        const float d1 = (float)acc[mi][p][rh * 2 + 1] * INVQ;
                        const float e0 = __expf(10.0f * d0);
                        const float e1 = __expf(10.0f * d1);
                        const int yi = yiv[mi][rh];
                        const float m0 = (yj0 == yi) ? 1.0f : 0.0f;
                        const float m1 = (yj1 == yi) ? 1.0f : 0.0f;
                        dnm[mi][rh] += e0 + e1;
                        Ss[mi][rh]  = fmaf(d0, m0, fmaf(d1, m1, Ss[mi][rh]));
                        mm[mi][rh] += m0 + m1;
                        cE0 += e0; cE1 += e1;
                        cS0 = fmaf(d0, m0, cS0); cS1 = fmaf(d1, m1, cS1);
                        cM0 += m0; cM1 += m1;
                    }
                const int s0 = jl * 36 + wi * 8 + grp, s1 = s0 + 36;
                jpE[s0] = cE0; jpE[s1] = cE1;
                jpS[s0] = cS0; jpS[s1] = cS1;
                jpM[s0] = cM0; jpM[s1] = cM1;
            }
        } else {
#pragma unroll
            for (int p = 0; p < 4; ++p) {
                const int jl = wj * 32 + p * 8 + 2 * (lane & 3);
                const int yj0 = yJ[jl], yj1 = yJ[jl + 1];
#pragma unroll
                for (int mi = 0; mi < 2; ++mi)
#pragma unroll
                    for (int rh = 0; rh < 2; ++rh) {
                        const float d0 = (float)acc[mi][p][rh * 2 + 0] * INVQ;
                        const float d1 = (float)acc[mi][p][rh * 2 + 1] * INVQ;
                        float e0 = __expf(10.0f * d0);
                        float e1 = __expf(10.0f * d1);
                        const int yi = yiv[mi][rh];
                        const int rowloc = wi * 32 + mi * 16 + rh * 8 + grp;
                        float m0 = (yj0 == yi) ? 1.0f : 0.0f;
                        float m1 = (yj1 == yi) ? 1.0f : 0.0f;
                        if (jl == rowloc)     { e0 = 0.0f; m0 = 0.0f; }
                        if (jl + 1 == rowloc) { e1 = 0.0f; m1 = 0.0f; }
                        dnm[mi][rh] += e0 + e1;
                        Ss[mi][rh]  = fmaf(d0, m0, fmaf(d1, m1, Ss[mi][rh]));
                        mm[mi][rh] += m0 + m1;
                    }
            }
        }

        // i-orientation per-thread partials: row slot = row*20 + wj*4 + (lane&3)
#pragma unroll
        for (int mi = 0; mi < 2; ++mi)
#pragma unroll
            for (int rh = 0; rh < 2; ++rh) {
                const int row = wi * 32 + mi * 16 + rh * 8 + grp;
                const int sl = row * 20 + wj * 4 + (lane & 3);
                ipE[sl] = dnm[mi][rh]; ipS[sl] = Ss[mi][rh]; ipM[sl] = mm[mi][rh];
            }
        __syncthreads();

        // store phase: sum partials, write g_P (each slot exactly once per launch)
        const int ntask = isDiag ? 384 : 768;
        for (int task = tid; task < ntask; task += THREADS) {
            if (task < 384) {
                const int stat = task >> 7, row = task & 127;
                const float* src = ipE + stat * 2560 + row * 20;
                float s = 0.f;
#pragma unroll
                for (int q = 0; q < 4; ++q) {
                    float4 v = *reinterpret_cast<const float4*>(src + q * 4);
                    s += (v.x + v.y) + (v.z + v.w);
                }
                g_P[stat * PLANE + bi * 8192 + bj * 128 + row] = s;
            } else {
                const int tt = task - 384;
                const int stat = tt >> 7, col = tt & 127;
                const float* src = jpE + stat * 4608 + col * 36;
                float s = 0.f;
#pragma unroll
                for (int q = 0; q < 8; ++q) {
                    float4 v = *reinterpret_cast<const float4*>(src + q * 4);
                    s += (v.x + v.y) + (v.z + v.w);
                }
                g_P[stat * PLANE + bj * 8192 + bi * 128 + col] = s;
            }
        }
        // loop-top CP_WAIT + __syncthreads orders partial-zone reuse next iteration
    }
}

// ---------------- Kernel 3: fused per-row loss + global sum ----------------
__global__ void __launch_bounds__(128) finish_kernel(float* __restrict__ out) {
    const int A = blockIdx.x, r = threadIdx.x;
    float D = 0.f, S = 0.f, M = 0.f;
    const int base = A * 8192 + r;
#pragma unroll 8
    for (int c = 0; c < 64; ++c) {
        D += g_P[base + c * 128];
        S += g_P[PLANE + base + c * 128];
        M += g_P[2 * PLANE + base + c * 128];
    }
    float v = (M > 0.5f) ? (logf(D) - 10.0f * S / M) : 0.0f;
    __shared__ float red[4];
#pragma unroll
    for (int o = 16; o; o >>= 1) v += __shfl_xor_sync(0xffffffffu, v, o);
    if ((r & 31) == 0) red[r >> 5] = v;
    __syncthreads();
    if (r == 0) {
        g_part[A] = (red[0] + red[1]) + (red[2] + red[3]);
        __threadfence();
        if (atomicAdd(&g_ctr, 1) == 63) {
            float s = 0.f;
#pragma unroll 8
            for (int i = 0; i < 64; ++i) s += g_part[i];
            out[0] = s;
            g_ctr = 0;     // reset for graph replay
        }
    }
}

// ---------------------------------------------------------------------------
extern "C" void kernel_launch(void* const* d_in, const int* in_sizes, int n_in,
                              void* d_out, int out_size) {
    (void)in_sizes; (void)n_in; (void)out_size;
    const float* x = (const float*)d_in[0];
    const int*   y = (const int*)d_in[1];
    float* out = (float*)d_out;

    cudaFuncSetAttribute(scl_mma_kernel,
                         cudaFuncAttributeMaxDynamicSharedMemorySize, SMEM_TOTAL);

    norm_kernel<<<NROW / 16, 256>>>(x);
    scl_mma_kernel<<<GRID, THREADS, SMEM_TOTAL>>>(y);
    finish_kernel<<<64, 128>>>(out);
}

// round 11
// speedup vs baseline: 1.5501x; 1.5501x over previous
#include <cuda_runtime.h>
#include <cuda_bf16.h>
#include <stdint.h>
#include <math.h>

#define NROW 8192
#define THREADS 512
#define GRID 148
#define STRIDE_B 272u            // 136 bf16 per smem row (17x16B, conflict-free)
#define TILEB (128u * STRIDE_B)  // 34816
#define BUFOFF(b) ((uint32_t)(b) * 2u * TILEB)   // A at +0, B at +TILEB
#define YOFF   (4u * TILEB)                       // 139264: 2 bufs x 1024B
#define IP_OFF (YOFF + 2048u)                     // 141312: 3 x 10240B (128 rows x 20 words)
#define JP_OFF (IP_OFF + 30720u)                  // 172032: 3 x 18432B (128 cols x 36 words)
#define SMEM_TOTAL (JP_OFF + 55296u)              // 227328 <= 232448

#define PLANE 524288             // 64*64*128 floats per stat plane

__device__ __nv_bfloat16 g_xb[NROW * 128];
// P[s][a][b][r]: s=0 denom, 1 S, 2 m. Every slot written exactly once per launch.
__device__ float g_P[3 * PLANE];
__device__ float g_part[64];
__device__ int   g_ctr;          // zero-init; self-resets each launch

// ---------------- PTX helpers ----------------
__device__ __forceinline__ uint32_t smem_u32(const void* p) {
    uint32_t a;
    asm("{ .reg .u64 t; cvta.to.shared.u64 t, %1; cvt.u32.u64 %0, t; }" : "=r"(a) : "l"(p));
    return a;
}
#define LDSM4(r, a) \
    asm volatile("ldmatrix.sync.aligned.m8n8.x4.shared.b16 {%0,%1,%2,%3}, [%4];" \
        : "=r"((r)[0]), "=r"((r)[1]), "=r"((r)[2]), "=r"((r)[3]) : "r"(a))
#define MMA16816(c, a, b0v, b1v) \
    asm volatile("mma.sync.aligned.m16n8k16.row.col.f32.bf16.bf16.f32 " \
        "{%0,%1,%2,%3}, {%4,%5,%6,%7}, {%8,%9}, {%0,%1,%2,%3};" \
        : "+f"((c)[0]), "+f"((c)[1]), "+f"((c)[2]), "+f"((c)[3]) \
        : "r"((a)[0]), "r"((a)[1]), "r"((a)[2]), "r"((a)[3]), "r"(b0v), "r"(b1v))
#define CP_ASYNC16(dst, src) \
    asm volatile("cp.async.cg.shared.global [%0], [%1], 16;" :: "r"(dst), "l"(src))
#define CP_ASYNC4(dst, src) \
    asm volatile("cp.async.ca.shared.global [%0], [%1], 4;" :: "r"(dst), "l"(src))
#define CP_COMMIT() asm volatile("cp.async.commit_group;" ::: "memory")
#define CP_WAIT1()  asm volatile("cp.async.wait_group 1;" ::: "memory")
#define CP_WAIT0()  asm volatile("cp.async.wait_group 0;" ::: "memory")

// ---------------- Kernel 1: normalize + bf16 convert (2 rows/warp) ----------------
__global__ void __launch_bounds__(256) norm_kernel(const float* __restrict__ x) {
    int warp = threadIdx.x >> 5, lane = threadIdx.x & 31;
    int row0 = (blockIdx.x * 8 + warp) * 2;
    float4 v0 = reinterpret_cast<const float4*>(x)[row0 * 32 + lane];
    float4 v1 = reinterpret_cast<const float4*>(x)[(row0 + 1) * 32 + lane];
    float s0 = v0.x * v0.x + v0.y * v0.y + v0.z * v0.z + v0.w * v0.w;
    float s1 = v1.x * v1.x + v1.y * v1.y + v1.z * v1.z + v1.w * v1.w;
#pragma unroll
    for (int o = 16; o; o >>= 1) {
        s0 += __shfl_xor_sync(0xffffffffu, s0, o);
        s1 += __shfl_xor_sync(0xffffffffu, s1, o);
    }
    float i0 = 1.0f / fmaxf(sqrtf(s0), 1e-12f);
    float i1 = 1.0f / fmaxf(sqrtf(s1), 1e-12f);
    v0.x *= i0; v0.y *= i0; v0.z *= i0; v0.w *= i0;
    v1.x *= i1; v1.y *= i1; v1.z *= i1; v1.w *= i1;
    uint32_t a0 = ((uint32_t)__bfloat16_as_ushort(__float2bfloat16(v0.y)) << 16)
                |  (uint32_t)__bfloat16_as_ushort(__float2bfloat16(v0.x));
    uint32_t a1 = ((uint32_t)__bfloat16_as_ushort(__float2bfloat16(v0.w)) << 16)
                |  (uint32_t)__bfloat16_as_ushort(__float2bfloat16(v0.z));
    uint32_t b0 = ((uint32_t)__bfloat16_as_ushort(__float2bfloat16(v1.y)) << 16)
                |  (uint32_t)__bfloat16_as_ushort(__float2bfloat16(v1.x));
    uint32_t b1 = ((uint32_t)__bfloat16_as_ushort(__float2bfloat16(v1.w)) << 16)
                |  (uint32_t)__bfloat16_as_ushort(__float2bfloat16(v1.z));
    reinterpret_cast<uint2*>(g_xb)[row0 * 32 + lane] = make_uint2(a0, a1);
    reinterpret_cast<uint2*>(g_xb)[(row0 + 1) * 32 + lane] = make_uint2(b0, b1);
}

// ---------------- off-diagonal index u in [0,2016) -> (bi, bj), bi < bj ----------------
__device__ __forceinline__ void offdiag(int u, int& bi, int& bj) {
    int k = (int)((1.0f + __fsqrt_rn(1.0f + 8.0f * (float)u)) * 0.5f);
    while (k * (k - 1) / 2 > u) --k;
    while ((k + 1) * k / 2 <= u) ++k;
    bi = 63 - k;
    bj = 63 - (u - k * (k - 1) / 2);
}

// Balanced schedule: CTAs 0-7 run 15 tiles (8 diagonal + 7 off-diag);
// CTAs 8-147 run 14 off-diag tiles. Diagonal tiles are cheaper (no
// j-orientation epilogue), offsetting the extra iteration.
__device__ __forceinline__ void sched(int b, int it, int& bi, int& bj) {
    if (b < 8) {
        if (it < 8) { bi = bj = b * 8 + it; return; }
        offdiag(b * 7 + (it - 8), bi, bj);
    } else {
        offdiag(56 + (b - 8) * 14 + it, bi, bj);
    }
}

__device__ __forceinline__ void prefetch_tile(uint32_t sbase, int buf,
                                              int bi, int bj, const uint4* xg,
                                              const int* y, int tid) {
    uint32_t dst = sbase + BUFOFF(buf);
    const int arow = bi * 128, brow = bj * 128;
#pragma unroll
    for (int q = 0; q < 4; ++q) {
        int idx = tid + q * THREADS;
        int row = idx >> 4, c16 = idx & 15;
        CP_ASYNC16(dst + row * STRIDE_B + c16 * 16, (const void*)(xg + (arow + row) * 16 + c16));
    }
#pragma unroll
    for (int q = 0; q < 4; ++q) {
        int idx = tid + q * THREADS;
        int row = idx >> 4, c16 = idx & 15;
        CP_ASYNC16(dst + TILEB + row * STRIDE_B + c16 * 16, (const void*)(xg + (brow + row) * 16 + c16));
    }
    if (tid < 128)
        CP_ASYNC4(sbase + YOFF + (uint32_t)buf * 1024u + tid * 4, (const void*)(y + arow + tid));
    else if (tid < 256)
        CP_ASYNC4(sbase + YOFF + (uint32_t)buf * 1024u + 512u + (tid - 128) * 4,
                  (const void*)(y + brow + (tid - 128)));
    CP_COMMIT();
}

// ---------------- Kernel 2: symmetric Gram + dual-orientation stats ----------------
__global__ void __launch_bounds__(THREADS, 1) scl_mma_kernel(const int* __restrict__ y) {
    extern __shared__ char smem[];
    const uint32_t sbase = smem_u32(smem);
    const int tid = threadIdx.x, wid = tid >> 5, lane = tid & 31;
    const int wi = wid & 3, wj = wid >> 2;
    const int grp = lane >> 2;
    const int b = blockIdx.x;
    const int niter = (b < 8) ? 15 : 14;

    const uint4* xg = reinterpret_cast<const uint4*>(g_xb);
    float* ipE = reinterpret_cast<float*>(smem + IP_OFF);          // 128 x 20 words
    float* ipS = ipE + 2560; float* ipM = ipE + 5120;
    float* jpE = reinterpret_cast<float*>(smem + JP_OFF);          // 128 x 36 words
    float* jpS = jpE + 4608; float* jpM = jpE + 9216;

    // relative ldmatrix offsets (buffer base added per tile)
    uint32_t aRel[2], bRel[2];
#pragma unroll
    for (int mi = 0; mi < 2; ++mi)
        aRel[mi] = (uint32_t)((wi * 32 + mi * 16 + (lane & 15)) * STRIDE_B + (lane >> 4) * 16);
#pragma unroll
    for (int nb = 0; nb < 2; ++nb)
        bRel[nb] = (uint32_t)((wj * 32 + nb * 16 + (lane & 7) + (lane >> 4) * 8) * STRIDE_B
                   + ((lane >> 3) & 1) * 16);

    {
        int bi0, bj0; sched(b, 0, bi0, bj0);
        prefetch_tile(sbase, 0, bi0, bj0, xg, y, tid);
    }

    for (int it = 0; it < niter; ++it) {
        int bi, bj; sched(b, it, bi, bj);
        if (it + 1 < niter) {
            int nbi, nbj; sched(b, it + 1, nbi, nbj);
            prefetch_tile(sbase, (it + 1) & 1, nbi, nbj, xg, y, tid);
            CP_WAIT1();
        } else {
            CP_WAIT0();
        }
        __syncthreads();

        const uint32_t abase = sbase + BUFOFF(it & 1);
        const uint32_t bbase = abase + TILEB;
        const int* yI = reinterpret_cast<const int*>(smem + YOFF + (it & 1) * 1024);
        const int* yJ = yI + 128;
        const bool isDiag = (bi == bj);

        float acc[2][4][4];
#pragma unroll
        for (int mi = 0; mi < 2; ++mi)
#pragma unroll
            for (int p = 0; p < 4; ++p)
#pragma unroll
                for (int c = 0; c < 4; ++c) acc[mi][p][c] = 0.f;

#pragma unroll
        for (int kk = 0; kk < 8; ++kk) {
            uint32_t a0[4], a1[4], b0[4], b1[4];
            LDSM4(a0, abase + aRel[0] + kk * 32);
            LDSM4(a1, abase + aRel[1] + kk * 32);
            LDSM4(b0, bbase + bRel[0] + kk * 32);
            LDSM4(b1, bbase + bRel[1] + kk * 32);
            MMA16816(acc[0][0], a0, b0[0], b0[1]);
            MMA16816(acc[0][1], a0, b0[2], b0[3]);
            MMA16816(acc[0][2], a0, b1[0], b1[1]);
            MMA16816(acc[0][3], a0, b1[2], b1[3]);
            MMA16816(acc[1][0], a1, b0[0], b0[1]);
            MMA16816(acc[1][1], a1, b0[2], b0[3]);
            MMA16816(acc[1][2], a1, b1[0], b1[1]);
            MMA16816(acc[1][3], a1, b1[2], b1[3]);
        }

        int yiv[2][2];
#pragma unroll
        for (int mi = 0; mi < 2; ++mi)
#pragma unroll
            for (int rh = 0; rh < 2; ++rh)
                yiv[mi][rh] = yI[wi * 32 + mi * 16 + rh * 8 + grp];

        float dnm[2][2] = {{0.f,0.f},{0.f,0.f}};
        float Ss [2][2] = {{0.f,0.f},{0.f,0.f}};
        float mm [2][2] = {{0.f,0.f},{0.f,0.f}};

        if (!isDiag) {
#pragma unroll
            for (int p = 0; p < 4; ++p) {
                const int jl = wj * 32 + (p >> 1) * 16 + (p & 1) * 8 + 2 * (lane & 3);
                const int yj0 = yJ[jl], yj1 = yJ[jl + 1];
                float cE0=0.f,cE1=0.f,cS0=0.f,cS1=0.f,cM0=0.f,cM1=0.f;
#pragma unroll
                for (int mi = 0; mi < 2; ++mi)
#pragma unroll
                    for (int rh = 0; rh < 2; ++rh) {
                        const float d0 = acc[mi][p][rh * 2 + 0];
                        const float d1 = acc[mi][p][rh * 2 + 1];
                        const float e0 = __expf(10.0f * d0);
                        const float e1 = __expf(10.0f * d1);
                        const int yi = yiv[mi][rh];
                        const float m0 = (yj0 == yi) ? 1.0f : 0.0f;
                        const float m1 = (yj1 == yi) ? 1.0f : 0.0f;
                        dnm[mi][rh] += e0 + e1;
                        Ss[mi][rh]  = fmaf(d0, m0, fmaf(d1, m1, Ss[mi][rh]));
                        mm[mi][rh] += m0 + m1;
                        cE0 += e0; cE1 += e1;
                        cS0 = fmaf(d0, m0, cS0); cS1 = fmaf(d1, m1, cS1);
                        cM0 += m0; cM1 += m1;
                    }
                const int s0 = jl * 36 + wi * 8 + grp, s1 = s0 + 36;
                jpE[s0] = cE0; jpE[s1] = cE1;
                jpS[s0] = cS0; jpS[s1] = cS1;
                jpM[s0] = cM0; jpM[s1] = cM1;
            }
        } else {
#pragma unroll
            for (int p = 0; p < 4; ++p) {
                const int jl = wj * 32 + (p >> 1) * 16 + (p & 1) * 8 + 2 * (lane & 3);
                const int yj0 = yJ[jl], yj1 = yJ[jl + 1];
#pragma unroll
                for (int mi = 0; mi < 2; ++mi)
#pragma unroll
                    for (int rh = 0; rh < 2; ++rh) {
                        const float d0 = acc[mi][p][rh * 2 + 0];
                        const float d1 = acc[mi][p][rh * 2 + 1];
                        float e0 = __expf(10.0f * d0);
                        float e1 = __expf(10.0f * d1);
                        const int yi = yiv[mi][rh];
                        const int rowloc = wi * 32 + mi * 16 + rh * 8 + grp;
                        float m0 = (yj0 == yi) ? 1.0f : 0.0f;
                        float m1 = (yj1 == yi) ? 1.0f : 0.0f;
                        if (jl == rowloc)     { e0 = 0.0f; m0 = 0.0f; }
                        if (jl + 1 == rowloc) { e1 = 0.0f; m1 = 0.0f; }
                        dnm[mi][rh] += e0 + e1;
                        Ss[mi][rh]  = fmaf(d0, m0, fmaf(d1, m1, Ss[mi][rh]));
                        mm[mi][rh] += m0 + m1;
                    }
            }
        }

        // i-orientation per-thread partials: row slot = row*20 + wj*4 + (lane&3)
#pragma unroll
        for (int mi = 0; mi < 2; ++mi)
#pragma unroll
            for (int rh = 0; rh < 2; ++rh) {
                const int row = wi * 32 + mi * 16 + rh * 8 + grp;
                const int sl = row * 20 + wj * 4 + (lane & 3);
                ipE[sl] = dnm[mi][rh]; ipS[sl] = Ss[mi][rh]; ipM[sl] = mm[mi][rh];
            }
        __syncthreads();

        // store phase: sum partials, write g_P (each slot exactly once per launch)
        const int ntask = isDiag ? 384 : 768;
        for (int task = tid; task < ntask; task += THREADS) {
            if (task < 384) {
                const int stat = task >> 7, row = task & 127;
                const float* src = ipE + stat * 2560 + row * 20;
                float s = 0.f;
#pragma unroll
                for (int q = 0; q < 4; ++q) {
                    float4 v = *reinterpret_cast<const float4*>(src + q * 4);
                    s += (v.x + v.y) + (v.z + v.w);
                }
                g_P[stat * PLANE + bi * 8192 + bj * 128 + row] = s;
            } else {
                const int tt = task - 384;
                const int stat = tt >> 7, col = tt & 127;
                const float* src = jpE + stat * 4608 + col * 36;
                float s = 0.f;
#pragma unroll
                for (int q = 0; q < 8; ++q) {
                    float4 v = *reinterpret_cast<const float4*>(src + q * 4);
                    s += (v.x + v.y) + (v.z + v.w);
                }
                g_P[stat * PLANE + bj * 8192 + bi * 128 + col] = s;
            }
        }
        // loop-top CP_WAIT + __syncthreads orders partial-zone reuse next iteration
    }
}

// ---------------- Kernel 3: fused per-row loss + global sum ----------------
__global__ void __launch_bounds__(128) finish_kernel(float* __restrict__ out) {
    const int A = blockIdx.x, r = threadIdx.x;
    float D = 0.f, S = 0.f, M = 0.f;
    const int base = A * 8192 + r;
#pragma unroll 8
    for (int c = 0; c < 64; ++c) {
        D += g_P[base + c * 128];
        S += g_P[PLANE + base + c * 128];
        M += g_P[2 * PLANE + base + c * 128];
    }
    float v = (M > 0.5f) ? (logf(D) - 10.0f * S / M) : 0.0f;
    __shared__ float red[4];
#pragma unroll
    for (int o = 16; o; o >>= 1) v += __shfl_xor_sync(0xffffffffu, v, o);
    if ((r & 31) == 0) red[r >> 5] = v;
    __syncthreads();
    if (r == 0) {
        g_part[A] = (red[0] + red[1]) + (red[2] + red[3]);
        __threadfence();
        if (atomicAdd(&g_ctr, 1) == 63) {
            float s = 0.f;
#pragma unroll 8
            for (int i = 0; i < 64; ++i) s += g_part[i];
            out[0] = s;
            g_ctr = 0;     // reset for graph replay
        }
    }
}

// ---------------------------------------------------------------------------
extern "C" void kernel_launch(void* const* d_in, const int* in_sizes, int n_in,
                              void* d_out, int out_size) {
    (void)in_sizes; (void)n_in; (void)out_size;
    const float* x = (const float*)d_in[0];
    const int*   y = (const int*)d_in[1];
    float* out = (float*)d_out;

    cudaFuncSetAttribute(scl_mma_kernel,
                         cudaFuncAttributeMaxDynamicSharedMemorySize, SMEM_TOTAL);

    norm_kernel<<<NROW / 16, 256>>>(x);
    scl_mma_kernel<<<GRID, THREADS, SMEM_TOTAL>>>(y);
    finish_kernel<<<64, 128>>>(out);
}